// round 1
// baseline (speedup 1.0000x reference)
#include <cuda_runtime.h>
#include <math.h>

#define MTOT 32768          // B * N = 8 * 4096
#define DD   512
#define BB   8
#define NTOK 4096
#define HH   64

// ---------------- scratch (static device globals; no runtime allocation) ----
__device__ float g_z[(size_t)MTOT * 1536];   // pre-activations [m][3*512]
__device__ float g_lam[(size_t)DD * MTOT];   // [d][m]
__device__ float g_inp[(size_t)DD * MTOT];   // [d][m]
__device__ float g_gate[(size_t)DD * MTOT];  // [d][m]
__device__ float g_hid[(size_t)DD * MTOT];   // [d][m]
__device__ float g_scale[MTOT];

// ---------------- K1: Z = x @ [Win | Wf | Wg]  (M=32768, K=512, N=1536) -----
__global__ __launch_bounds__(256, 2) void k1_gemm(
    const float* __restrict__ x,
    const float* __restrict__ Win,
    const float* __restrict__ Wf,
    const float* __restrict__ Wg)
{
    __shared__ float As[2][8][128];
    __shared__ float Bs[2][8][128];
    const int bn0 = blockIdx.x * 128;
    const int bm0 = blockIdx.y * 128;
    const int sec = bn0 >> 9;                     // which weight (uniform per block)
    const float* Wp = (sec == 0) ? Win : ((sec == 1) ? Wf : Wg);
    const int nb = bn0 & 511;
    const int tid = threadIdx.x;

    const int a_row = tid >> 1;                   // 0..127
    const int a_col = (tid & 1) << 2;             // 0 or 4
    const int b_row = tid >> 5;                   // 0..7
    const int b_col = (tid & 31) << 2;            // 0..124
    const float* Aptr = x + (size_t)(bm0 + a_row) * 512 + a_col;
    const float* Bptr = Wp + (size_t)b_row * 512 + nb + b_col;
    const int tx = tid & 15, ty = tid >> 4;

    float acc[8][8];
#pragma unroll
    for (int i = 0; i < 8; i++)
#pragma unroll
        for (int j = 0; j < 8; j++) acc[i][j] = 0.f;

    float4 av = *(const float4*)Aptr;
    float4 bv = *(const float4*)Bptr;
    As[0][a_col + 0][a_row] = av.x; As[0][a_col + 1][a_row] = av.y;
    As[0][a_col + 2][a_row] = av.z; As[0][a_col + 3][a_row] = av.w;
    *(float4*)&Bs[0][b_row][b_col] = bv;
    __syncthreads();

    int buf = 0;
    for (int k0 = 0; k0 < 512; k0 += 8) {
        const bool more = (k0 + 8) < 512;
        if (more) {
            av = *(const float4*)(Aptr + k0 + 8);
            bv = *(const float4*)(Bptr + (size_t)(k0 + 8) * 512);
        }
#pragma unroll
        for (int kk = 0; kk < 8; kk++) {
            float a[8], b[8];
            *(float4*)&a[0] = *(const float4*)&As[buf][kk][ty * 4];
            *(float4*)&a[4] = *(const float4*)&As[buf][kk][64 + ty * 4];
            *(float4*)&b[0] = *(const float4*)&Bs[buf][kk][tx * 4];
            *(float4*)&b[4] = *(const float4*)&Bs[buf][kk][64 + tx * 4];
#pragma unroll
            for (int i = 0; i < 8; i++)
#pragma unroll
                for (int j = 0; j < 8; j++) acc[i][j] += a[i] * b[j];
        }
        if (more) {
            buf ^= 1;
            As[buf][a_col + 0][a_row] = av.x; As[buf][a_col + 1][a_row] = av.y;
            As[buf][a_col + 2][a_row] = av.z; As[buf][a_col + 3][a_row] = av.w;
            *(float4*)&Bs[buf][b_row][b_col] = bv;
            __syncthreads();
        }
    }
#pragma unroll
    for (int i = 0; i < 8; i++) {
        const int m = bm0 + ((i < 4) ? (ty * 4 + i) : (64 + ty * 4 + i - 4));
        float* orow = g_z + (size_t)m * 1536 + bn0;
        *(float4*)&orow[tx * 4]      = make_float4(acc[i][0], acc[i][1], acc[i][2], acc[i][3]);
        *(float4*)&orow[64 + tx * 4] = make_float4(acc[i][4], acc[i][5], acc[i][6], acc[i][7]);
    }
}

// ---------------- K2: activations + transpose to [d][m] ---------------------
__global__ void k2_act(const float* __restrict__ b_in,
                       const float* __restrict__ b_f,
                       const float* __restrict__ b_g,
                       const float* __restrict__ lb)
{
    __shared__ float sl[32][33], si[32][33], sg[32][33];
    const int m0 = blockIdx.x * 32, d0 = blockIdx.y * 32;
    const int tx = threadIdx.x, ty = threadIdx.y;   // 32 x 8
    const float lbv = lb[0];
#pragma unroll
    for (int r = 0; r < 4; r++) {
        const int m = m0 + ty + r * 8;
        const int d = d0 + tx;
        const float* zr = g_z + (size_t)m * 1536;
        const float zi = zr[d]        + b_in[d];
        const float zf = zr[512 + d]  + b_f[d];
        const float zg = zr[1024 + d] + b_g[d];
        const float u   = zi / (1.f + expf(-zi));                 // silu
        const float lam = lbv + (1.f - lbv) / (1.f + expf(-zf));  // bounded decay
        sl[ty + r * 8][tx] = lam;
        si[ty + r * 8][tx] = (1.f - lam) * u;
        sg[ty + r * 8][tx] = 1.f / (1.f + expf(-zg));
    }
    __syncthreads();
#pragma unroll
    for (int r = 0; r < 4; r++) {
        const int d = d0 + ty + r * 8;
        const int m = m0 + tx;
        const size_t o = (size_t)d * MTOT + m;
        g_lam[o]  = sl[tx][ty + r * 8];
        g_inp[o]  = si[tx][ty + r * 8];
        g_gate[o] = sg[tx][ty + r * 8];
    }
}

// ---------------- K3: 4-direction complex gated scan on 64x64 tile ----------
// One block per (d, b). smem pad 65 -> conflict-free row AND column access.
__global__ void k3_scan(const float* __restrict__ theta)
{
    extern __shared__ float sm[];
    float* sl = sm;                 // 64*65
    float* si = sm + 64 * 65;       // 64*65
    float* sh = sm + 2 * 64 * 65;   // 64*65
    const int d = blockIdx.x;
    const int b = blockIdx.y;
    const size_t base = (size_t)d * MTOT + (size_t)b * NTOK;
    const int t = threadIdx.x;      // 0..63

#pragma unroll 8
    for (int i = t; i < 4096; i += 64) {
        const int r = i >> 6, c = i & 63;
        sl[r * 65 + c] = g_lam[base + i];
        si[r * 65 + c] = g_inp[base + i];
        sh[r * 65 + c] = 0.f;
    }
    const float th = theta[d];
    const float cth = cosf(th), sth = sinf(th);
    __syncthreads();

    // axis 1 (over c within row t): forward then backward
    {
        const float* lrow = sl + t * 65;
        const float* irow = si + t * 65;
        float* hrow = sh + t * 65;
        float hr = 0.f, hi = 0.f;
        for (int s2 = 0; s2 < 64; s2++) {
            const float lam = lrow[s2];
            const float lc = lam * cth, ls = lam * sth;
            const float nr = lc * hr - ls * hi + irow[s2];
            hi = ls * hr + lc * hi;
            hr = nr;
            hrow[s2] += hr;
        }
        hr = 0.f; hi = 0.f;
        for (int s2 = 63; s2 >= 0; s2--) {
            const float lam = lrow[s2];
            const float lc = lam * cth, ls = lam * sth;
            const float nr = lc * hr - ls * hi + irow[s2];
            hi = ls * hr + lc * hi;
            hr = nr;
            hrow[s2] += hr;
        }
    }
    __syncthreads();
    // axis 0 (over r within column t): forward then backward
    {
        float hr = 0.f, hi = 0.f;
        for (int s2 = 0; s2 < 64; s2++) {
            const float lam = sl[s2 * 65 + t];
            const float lc = lam * cth, ls = lam * sth;
            const float nr = lc * hr - ls * hi + si[s2 * 65 + t];
            hi = ls * hr + lc * hi;
            hr = nr;
            sh[s2 * 65 + t] += hr;
        }
        hr = 0.f; hi = 0.f;
        for (int s2 = 63; s2 >= 0; s2--) {
            const float lam = sl[s2 * 65 + t];
            const float lc = lam * cth, ls = lam * sth;
            const float nr = lc * hr - ls * hi + si[s2 * 65 + t];
            hi = ls * hr + lc * hi;
            hr = nr;
            sh[s2 * 65 + t] += hr;
        }
    }
    __syncthreads();
#pragma unroll 8
    for (int i = t; i < 4096; i += 64) {
        const int r = i >> 6, c = i & 63;
        g_hid[base + i] = sh[r * 65 + c];
    }
}

// ---------------- K4: per-row RMS scale -------------------------------------
__global__ void k4_scale()
{
    const int m = blockIdx.x * 256 + threadIdx.x;
    float acc = 0.f;
#pragma unroll 8
    for (int d = 0; d < 512; d++) {
        const float v = g_hid[(size_t)d * MTOT + m];
        acc += v * v;
    }
    g_scale[m] = rsqrtf(acc * (1.f / 512.f) + 1e-6f);
}

// ---------------- K5: Y = (g .* hid .* scale) @ Wout + bout -----------------
// A is stored K-major ([d][m]) -> direct coalesced float4 A-tile loads.
__global__ __launch_bounds__(256, 2) void k5_gemm(
    const float* __restrict__ Wout,
    const float* __restrict__ bout,
    float* __restrict__ out)
{
    __shared__ float As[2][8][128];
    __shared__ float Bs[2][8][128];
    const int bn0 = blockIdx.x * 128;
    const int bm0 = blockIdx.y * 128;
    const int tid = threadIdx.x;

    const int ak = tid >> 5;                 // k row 0..7
    const int am = (tid & 31) << 2;          // m offset 0..124
    const int b_row = tid >> 5;
    const int b_col = (tid & 31) << 2;
    const float* Bptr = Wout + (size_t)b_row * 512 + bn0 + b_col;
    const int tx = tid & 15, ty = tid >> 4;

    const float4 sv = *(const float4*)&g_scale[bm0 + am];

    float acc[8][8];
#pragma unroll
    for (int i = 0; i < 8; i++)
#pragma unroll
        for (int j = 0; j < 8; j++) acc[i][j] = 0.f;

    float4 hv = *(const float4*)&g_hid[(size_t)ak * MTOT + bm0 + am];
    float4 gv = *(const float4*)&g_gate[(size_t)ak * MTOT + bm0 + am];
    float4 bv = *(const float4*)Bptr;
    As[0][ak][am + 0] = hv.x * gv.x * sv.x;
    As[0][ak][am + 1] = hv.y * gv.y * sv.y;
    As[0][ak][am + 2] = hv.z * gv.z * sv.z;
    As[0][ak][am + 3] = hv.w * gv.w * sv.w;
    *(float4*)&Bs[0][b_row][b_col] = bv;
    __syncthreads();

    int buf = 0;
    for (int k0 = 0; k0 < 512; k0 += 8) {
        const bool more = (k0 + 8) < 512;
        if (more) {
            hv = *(const float4*)&g_hid [(size_t)(k0 + 8 + ak) * MTOT + bm0 + am];
            gv = *(const float4*)&g_gate[(size_t)(k0 + 8 + ak) * MTOT + bm0 + am];
            bv = *(const float4*)(Bptr + (size_t)(k0 + 8) * 512);
        }
#pragma unroll
        for (int kk = 0; kk < 8; kk++) {
            float a[8], b[8];
            *(float4*)&a[0] = *(const float4*)&As[buf][kk][ty * 4];
            *(float4*)&a[4] = *(const float4*)&As[buf][kk][64 + ty * 4];
            *(float4*)&b[0] = *(const float4*)&Bs[buf][kk][tx * 4];
            *(float4*)&b[4] = *(const float4*)&Bs[buf][kk][64 + tx * 4];
#pragma unroll
            for (int i = 0; i < 8; i++)
#pragma unroll
                for (int j = 0; j < 8; j++) acc[i][j] += a[i] * b[j];
        }
        if (more) {
            buf ^= 1;
            As[buf][ak][am + 0] = hv.x * gv.x * sv.x;
            As[buf][ak][am + 1] = hv.y * gv.y * sv.y;
            As[buf][ak][am + 2] = hv.z * gv.z * sv.z;
            As[buf][ak][am + 3] = hv.w * gv.w * sv.w;
            *(float4*)&Bs[buf][b_row][b_col] = bv;
            __syncthreads();
        }
    }

    const float4 bo0 = *(const float4*)&bout[bn0 + tx * 4];
    const float4 bo1 = *(const float4*)&bout[bn0 + 64 + tx * 4];
#pragma unroll
    for (int i = 0; i < 8; i++) {
        const int m = bm0 + ((i < 4) ? (ty * 4 + i) : (64 + ty * 4 + i - 4));
        float* orow = out + (size_t)m * 512 + bn0;
        *(float4*)&orow[tx * 4] = make_float4(acc[i][0] + bo0.x, acc[i][1] + bo0.y,
                                              acc[i][2] + bo0.z, acc[i][3] + bo0.w);
        *(float4*)&orow[64 + tx * 4] = make_float4(acc[i][4] + bo1.x, acc[i][5] + bo1.y,
                                                   acc[i][6] + bo1.z, acc[i][7] + bo1.w);
    }
}

// ---------------- launch ----------------------------------------------------
extern "C" void kernel_launch(void* const* d_in, const int* in_sizes, int n_in,
                              void* d_out, int out_size)
{
    const float* x    = (const float*)d_in[0];
    const float* lb   = (const float*)d_in[1];
    const float* Win  = (const float*)d_in[2];
    const float* bin  = (const float*)d_in[3];
    const float* Wf   = (const float*)d_in[4];
    const float* bf   = (const float*)d_in[5];
    const float* th   = (const float*)d_in[6];
    const float* Wg   = (const float*)d_in[7];
    const float* bg   = (const float*)d_in[8];
    const float* Wout = (const float*)d_in[9];
    const float* bout = (const float*)d_in[10];
    float* out = (float*)d_out;

    k1_gemm<<<dim3(12, 256), 256>>>(x, Win, Wf, Wg);
    k2_act<<<dim3(MTOT / 32, DD / 32), dim3(32, 8)>>>(bin, bf, bg, lb);

    const int scan_smem = 3 * 64 * 65 * 4;   // 49,920 B > 48 KB -> opt-in
    cudaFuncSetAttribute(k3_scan, cudaFuncAttributeMaxDynamicSharedMemorySize, scan_smem);
    k3_scan<<<dim3(DD, BB), 64, scan_smem>>>(th);

    k4_scale<<<MTOT / 256, 256>>>();
    k5_gemm<<<dim3(4, 256), 256>>>(Wout, bout, out);
}